// round 15
// baseline (speedup 1.0000x reference)
#include <cuda_runtime.h>
#include <cuda_fp16.h>
#include <cstdint>
#include <math.h>

typedef unsigned int u32;

#define DM   1024
#define G4   4096
#define NB   128
#define NS   1024
#define NC   512
#define NCTA 128
#define PH_STEP 65536

// ---------------- device scratch (static, no allocation) ----------------
__device__ float g_G[NC * G4];              // 8 MB
__device__ u32   g_PH[NS * PH_STEP];        // 256 MB fp16 h history, fragment-packed
__device__ uint4 g_WpPack[8 * 64 * 4 * 32]; // 1 MB W_pred fp16 B-fragment order
__device__ unsigned char g_flagc[NS * 128]; // one 128B flag line per step

__device__ __forceinline__ u32 sm2u(const void* p) {
    u32 a;
    asm("{ .reg .u64 t; cvta.to.shared.u64 t, %1; cvt.u32.u64 %0, t; }" : "=r"(a) : "l"(p));
    return a;
}
#define CP_ASYNC16(dst, src) \
    asm volatile("cp.async.ca.shared.global [%0], [%1], 16;" :: "r"(dst), "l"(src))
#define CP_COMMIT() asm volatile("cp.async.commit_group;" ::: "memory")
#define CP_WAIT0()  asm volatile("cp.async.wait_group 0;" ::: "memory")

// ============ fp32 NT GEMM for G (known-good) ============
__global__ void gemm_nt_kernel(const float* __restrict__ A, const float* __restrict__ Bm,
                               const float* __restrict__ bias0, const float* __restrict__ bias1,
                               float* __restrict__ Cout, int M, int N, int K)
{
    __shared__ float As[16][64];
    __shared__ float Bs[16][64];
    const int tid = threadIdx.x;
    const int tx = tid & 15, ty = tid >> 4;
    const int mBase = blockIdx.x * 64, nBase = blockIdx.y * 64;
    const int la = tid >> 2, lk = (tid & 3) * 4;

    float acc[4][4];
#pragma unroll
    for (int i = 0; i < 4; i++)
#pragma unroll
        for (int j = 0; j < 4; j++) acc[i][j] = 0.f;

    for (int kc = 0; kc < K; kc += 16) {
        {
            float4 v = *reinterpret_cast<const float4*>(&A[(size_t)(mBase + la) * K + kc + lk]);
            As[lk + 0][la] = v.x; As[lk + 1][la] = v.y; As[lk + 2][la] = v.z; As[lk + 3][la] = v.w;
        }
        {
            float4 v = *reinterpret_cast<const float4*>(&Bm[(size_t)(nBase + la) * K + kc + lk]);
            Bs[lk + 0][la] = v.x; Bs[lk + 1][la] = v.y; Bs[lk + 2][la] = v.z; Bs[lk + 3][la] = v.w;
        }
        __syncthreads();
#pragma unroll
        for (int k = 0; k < 16; k++) {
            float4 a4 = *reinterpret_cast<const float4*>(&As[k][tx * 4]);
            float4 b4 = *reinterpret_cast<const float4*>(&Bs[k][ty * 4]);
            float a[4] = {a4.x, a4.y, a4.z, a4.w};
            float b[4] = {b4.x, b4.y, b4.z, b4.w};
#pragma unroll
            for (int i = 0; i < 4; i++)
#pragma unroll
                for (int j = 0; j < 4; j++)
                    acc[i][j] = fmaf(a[i], b[j], acc[i][j]);
        }
        __syncthreads();
    }
#pragma unroll
    for (int i = 0; i < 4; i++) {
        int row = mBase + tx * 4 + i;
#pragma unroll
        for (int j = 0; j < 4; j++) {
            int col = nBase + ty * 4 + j;
            Cout[(size_t)row * N + col] = acc[i][j] + bias0[col] + bias1[col];
        }
    }
}

// ---- fast, saturating-safe activations ----
__device__ __forceinline__ float fast_sigmoid(float x) { return 1.f / (1.f + __expf(-x)); }
__device__ __forceinline__ float fast_tanh(float x)    { return 1.f - 2.f / (1.f + __expf(2.f * x)); }

#define MMA16816(C, A0, A1, A2, A3, B0, B1)                                   \
    asm volatile(                                                             \
        "mma.sync.aligned.m16n8k16.row.col.f32.f16.f16.f32 "                  \
        "{%0,%1,%2,%3}, {%4,%5,%6,%7}, {%8,%9}, {%0,%1,%2,%3};"               \
        : "+f"(C[0]), "+f"(C[1]), "+f"(C[2]), "+f"(C[3])                      \
        : "r"(A0), "r"(A1), "r"(A2), "r"(A3), "r"(B0), "r"(B1))

// ============ pack W_pred -> fp16 B-fragment order (known-good) ============
__global__ void pack_wpred_kernel(const float* __restrict__ Wp)
{
    int idx = blockIdx.x * 256 + threadIdx.x;
    int lane = idx & 31, q = (idx >> 5) & 3, it = (idx >> 7) & 63, nb = idx >> 13;
    u32 v[4];
#pragma unroll
    for (int h = 0; h < 2; h++) {
        int t = 2 * q + h;
        int n = nb * 64 + t * 8 + (lane >> 2);
        const float* row = Wp + (size_t)n * DM;
        int j0 = it * 8 + (lane & 3), j1 = j0 + 4;
        __half2 p0 = __floats2half2_rn(row[2 * j0], row[2 * j0 + 1]);
        __half2 p1 = __floats2half2_rn(row[2 * j1], row[2 * j1 + 1]);
        v[2 * h + 0] = *reinterpret_cast<u32*>(&p0);
        v[2 * h + 1] = *reinterpret_cast<u32*>(&p1);
    }
    g_WpPack[idx] = make_uint4(v[0], v[1], v[2], v[3]);
}

// =========================================================================
// Persistent LSTM (R10 compute scheme) + cp.async G staging + byte-flag barrier.
// 128 CTAs x 256 threads. Warp w = (bh = w&1, q = w>>1): M=64, K=256, N=32.
// W_hh fragments in registers; split-K=4 via padded smem.
// G rows for step s staged into SMEM via cp.async at step top (overlaps mma);
// cell phase reads them with LDS. Barrier: 1 byte-store release per CTA into a
// single 128B line, warp-0 coalesced poll.
// =========================================================================
#define RSTRIDE 36
#define GSTRIDE 36                       // floats per staged batch row (144 B, 16B-aligned)
#define RED_FLOATS (4 * 128 * RSTRIDE)   // 18432
#define GS_FLOATS  (128 * GSTRIDE)       // 4608
#define SMEM_BYTES ((RED_FLOATS + GS_FLOATS) * 4)

__global__ void __launch_bounds__(256, 1)
lstm_mma_kernel(const int* __restrict__ x, const float* __restrict__ Whh)
{
    extern __shared__ float smem_f[];
    float* red = smem_f;                 // split-K exchange
    float* Gs  = smem_f + RED_FLOATS;    // staged G rows [128 b][4 g][8 f] stride 36

    const int tid  = threadIdx.x;
    const int lane = tid & 31;
    const int w    = tid >> 5;           // 0..7
    const int bh   = w & 1;              // batch half
    const int q    = w >> 1;             // k quarter
    const int d0   = blockIdx.x * 8;
    const int tig  = lane & 3;
    const int grp  = lane >> 2;
    const int cta  = blockIdx.x;

    // staging identity: thread -> (batch sb, half sh)
    const int sb = tid >> 1;
    const int sh = tid & 1;
    const u32 gsDst = sm2u(Gs) + (u32)(sb * (GSTRIDE * 4) + sh * 16);
    const float* gSrcBase = g_G + d0 + sh * 4;

    // ---- one-time: W_hh fragments -> registers (proven fragment math) ----
    u32 wreg[128];
    {
        const int kbase = q * 256 + 2 * tig;
#pragma unroll
        for (int it = 0; it < 16; it++) {
#pragma unroll
            for (int n = 0; n < 4; n++) {
                const float* Wr = Whh + (size_t)(n * DM + d0 + grp) * DM + kbase + it * 16;
                __half2 p0 = __floats2half2_rn(Wr[0], Wr[1]);
                __half2 p1 = __floats2half2_rn(Wr[8], Wr[9]);
                wreg[it * 8 + n * 2 + 0] = *reinterpret_cast<u32*>(&p0);
                wreg[it * 8 + n * 2 + 1] = *reinterpret_cast<u32*>(&p1);
            }
        }
    }

    // ---- cell-update ownership (proven R5 scheme) ----
    const int b_lo = w * 16 + grp;
    const int b_hi = b_lo + 8;
    const int k2   = (d0 >> 1) + tig;
    const int p8   = k2 & 7;
    const int slot = (p8 < 4) ? (2 * p8) : (2 * (p8 - 4) + 1);
    const int wIdx = (w * 8 + grp) * 1024 + ((k2 >> 3) * 8 + slot) * 2;

    int aBase[4];
#pragma unroll
    for (int t = 0; t < 4; t++)
        aBase[t] = ((4 * bh + t) * 8 + grp) * 1024 + 4 * tig + q * 256;

    float cr[4] = {0.f, 0.f, 0.f, 0.f};

    for (int s = 0; s < NS; s++) {
        // ---- stage G[x[s]] rows into SMEM via cp.async (overlaps the mma) ----
        {
            const int xv = __ldg(&x[s * NB + sb]);
            const float* src = gSrcBase + (size_t)xv * G4;
#pragma unroll
            for (int g = 0; g < 4; g++)
                CP_ASYNC16(gsDst + g * 32, src + g * DM);
            CP_COMMIT();
        }

        float acc[4][4][4];              // [mtile][ntile=gate][c]
#pragma unroll
        for (int t = 0; t < 4; t++)
#pragma unroll
            for (int n = 0; n < 4; n++)
#pragma unroll
                for (int jj = 0; jj < 4; jj++) acc[t][n][jj] = 0.f;

        if (s > 0) {
            const u32* ph = g_PH + (size_t)(s - 1) * PH_STEP;
#pragma unroll
            for (int it = 0; it < 16; it++) {
                uint4 a0 = *reinterpret_cast<const uint4*>(ph + aBase[0] + it * 16);
                uint4 a1 = *reinterpret_cast<const uint4*>(ph + aBase[1] + it * 16);
                uint4 a2 = *reinterpret_cast<const uint4*>(ph + aBase[2] + it * 16);
                uint4 a3 = *reinterpret_cast<const uint4*>(ph + aBase[3] + it * 16);
#pragma unroll
                for (int n = 0; n < 4; n++) {
                    u32 w0 = wreg[it * 8 + 2 * n], w1 = wreg[it * 8 + 2 * n + 1];
                    MMA16816(acc[0][n], a0.x, a0.y, a0.z, a0.w, w0, w1);
                    MMA16816(acc[1][n], a1.x, a1.y, a1.z, a1.w, w0, w1);
                    MMA16816(acc[2][n], a2.x, a2.y, a2.z, a2.w, w0, w1);
                    MMA16816(acc[3][n], a3.x, a3.y, a3.z, a3.w, w0, w1);
                }
            }
        }

        // ---- publish split-K partials ----
        {
            float* rq = red + q * (128 * RSTRIDE);
#pragma unroll
            for (int t = 0; t < 4; t++) {
                int r0 = 64 * bh + 16 * t + grp;
#pragma unroll
                for (int n = 0; n < 4; n++) {
                    int col = 8 * n + 2 * tig;
                    *reinterpret_cast<float2*>(rq + r0 * RSTRIDE + col) =
                        make_float2(acc[t][n][0], acc[t][n][1]);
                    *reinterpret_cast<float2*>(rq + (r0 + 8) * RSTRIDE + col) =
                        make_float2(acc[t][n][2], acc[t][n][3]);
                }
            }
        }
        CP_WAIT0();          // staged G resident before the barrier below
        __syncthreads();

        // ---- reduce 4 quarters + thread-local LSTM cell update ----
        {
            // staged G reads (LDS, 2-way conflicts worst case)
            float gl[4][2], gh[4][2];
#pragma unroll
            for (int g = 0; g < 4; g++) {
                float2 v = *reinterpret_cast<const float2*>(Gs + b_lo * GSTRIDE + g * 8 + 2 * tig);
                gl[g][0] = v.x; gl[g][1] = v.y;
                float2 u = *reinterpret_cast<const float2*>(Gs + b_hi * GSTRIDE + g * 8 + 2 * tig);
                gh[g][0] = u.x; gh[g][1] = u.y;
            }

            float sum[2][4][2];
#pragma unroll
            for (int g = 0; g < 4; g++) {
                float sLx = 0.f, sLy = 0.f, sHx = 0.f, sHy = 0.f;
#pragma unroll
                for (int qq = 0; qq < 4; qq++) {
                    const float* rq = red + qq * (128 * RSTRIDE);
                    float2 vL = *reinterpret_cast<const float2*>(rq + b_lo * RSTRIDE + 8 * g + 2 * tig);
                    float2 vH = *reinterpret_cast<const float2*>(rq + b_hi * RSTRIDE + 8 * g + 2 * tig);
                    sLx += vL.x; sLy += vL.y; sHx += vH.x; sHy += vH.y;
                }
                sum[0][g][0] = sLx; sum[0][g][1] = sLy;
                sum[1][g][0] = sHx; sum[1][g][1] = sHy;
            }

            u32 h2out[2];
#pragma unroll
            for (int p = 0; p < 2; p++) {
                float hv[2];
#pragma unroll
                for (int e = 0; e < 2; e++) {
                    float ai = sum[p][0][e] + (p ? gh[0][e] : gl[0][e]);
                    float af = sum[p][1][e] + (p ? gh[1][e] : gl[1][e]);
                    float ag = sum[p][2][e] + (p ? gh[2][e] : gl[2][e]);
                    float ao = sum[p][3][e] + (p ? gh[3][e] : gl[3][e]);

                    float iv = fast_sigmoid(ai);
                    float fv = fast_sigmoid(af);
                    float gv = fast_tanh(ag);
                    float ov = fast_sigmoid(ao);

                    float cnew = fmaf(fv, cr[p * 2 + e], iv * gv);
                    cr[p * 2 + e] = cnew;
                    hv[e] = ov * fast_tanh(cnew);
                }
                __half2 hh = __floats2half2_rn(hv[0], hv[1]);
                h2out[p] = *reinterpret_cast<u32*>(&hh);
            }
            *reinterpret_cast<uint2*>(g_PH + (size_t)s * PH_STEP + wIdx) =
                make_uint2(h2out[0], h2out[1]);
        }

        // ---- byte-flag barrier: 1 store/CTA into one 128B line, warp-0 poll ----
        __threadfence();
        __syncthreads();
        if (tid == 0)
            *((volatile unsigned char*)&g_flagc[s * 128 + cta]) = 1;
        if (w == 0) {
            const volatile u32* f = (const volatile u32*)(g_flagc + s * 128);
            int done;
            do {
                u32 v = f[lane];
                done = __all_sync(0xffffffffu, v == 0x01010101u);
            } while (!done);
        }
        __syncthreads();
        __threadfence();
    }
}

// Reset flag lines for deterministic graph replay.
__global__ void reset_flag_kernel()
{
    ((u32*)g_flagc)[blockIdx.x * 256 + threadIdx.x] = 0;
}

// ============ logits: PH(fp16) @ W_pred^T + bias via warp mma (known-good) ============
__global__ void __launch_bounds__(256, 1)
logits_mma_kernel(const float* __restrict__ bias, float* __restrict__ out)
{
    extern __shared__ uint4 wb[];        // 8192 uint4 = 128 KB
    const int tid = threadIdx.x;
    const int lane = tid & 31, w = tid >> 5;
    const int nb = blockIdx.x, s = blockIdx.y;
    const int grp = lane >> 2, tig = lane & 3;

    for (int i = tid; i < 8192; i += 256) wb[i] = g_WpPack[nb * 8192 + i];
    __syncthreads();

    const u32* ph   = g_PH + (size_t)s * PH_STEP;
    const int aBase = (w * 8 + grp) * 1024 + 4 * tig;

    float acc[8][4];
#pragma unroll
    for (int t = 0; t < 8; t++)
#pragma unroll
        for (int j = 0; j < 4; j++) acc[t][j] = 0.f;

#pragma unroll 2
    for (int it = 0; it < 64; it++) {
        uint4 a = *reinterpret_cast<const uint4*>(ph + aBase + it * 16);
#pragma unroll
        for (int qq = 0; qq < 4; qq++) {
            uint4 wq = wb[it * 128 + qq * 32 + lane];
            MMA16816(acc[2 * qq],     a.x, a.y, a.z, a.w, wq.x, wq.y);
            MMA16816(acc[2 * qq + 1], a.x, a.y, a.z, a.w, wq.z, wq.w);
        }
    }

    const int bL = w * 16 + grp, bH = bL + 8;
#pragma unroll
    for (int t = 0; t < 8; t++) {
        int col = nb * 64 + t * 8 + 2 * tig;
        float2 bz = *reinterpret_cast<const float2*>(bias + col);
        *reinterpret_cast<float2*>(out + (size_t)bL * NS * NC + (size_t)s * NC + col) =
            make_float2(acc[t][0] + bz.x, acc[t][1] + bz.y);
        *reinterpret_cast<float2*>(out + (size_t)bH * NS * NC + (size_t)s * NC + col) =
            make_float2(acc[t][2] + bz.x, acc[t][3] + bz.y);
    }
}

// =========================================================================
extern "C" void kernel_launch(void* const* d_in, const int* in_sizes, int n_in,
                              void* d_out, int out_size)
{
    const int*   x      = (const int*)  d_in[0];
    const float* emb    = (const float*)d_in[1];
    const float* W_ih   = (const float*)d_in[2];
    const float* W_hh   = (const float*)d_in[3];
    const float* b_ih   = (const float*)d_in[4];
    const float* b_hh   = (const float*)d_in[5];
    const float* W_pred = (const float*)d_in[6];
    const float* b_pred = (const float*)d_in[7];
    float* out = (float*)d_out;

    float* Gp; cudaGetSymbolAddress((void**)&Gp, g_G);

    // 1) G = emb @ W_ih^T + b_ih + b_hh
    {
        dim3 grid(NC / 64, G4 / 64);
        gemm_nt_kernel<<<grid, 256>>>(emb, W_ih, b_ih, b_hh, Gp, NC, G4, DM);
    }
    // 2) pack W_pred
    pack_wpred_kernel<<<256, 256>>>(W_pred);
    // 3) persistent LSTM (R10 + staged G + byte-flag barrier)
    {
        cudaFuncSetAttribute(lstm_mma_kernel,
                             cudaFuncAttributeMaxDynamicSharedMemorySize, SMEM_BYTES);
        lstm_mma_kernel<<<NCTA, 256, SMEM_BYTES>>>(x, W_hh);
    }
    // 4) reset flag lines
    reset_flag_kernel<<<128, 256>>>();
    // 5) logits
    {
        const int smem_bytes = 8192 * (int)sizeof(uint4);
        cudaFuncSetAttribute(logits_mma_kernel,
                             cudaFuncAttributeMaxDynamicSharedMemorySize, smem_bytes);
        dim3 grid(8, NS);
        logits_mma_kernel<<<grid, 256, smem_bytes>>>(b_pred, out);
    }
}

// round 16
// speedup vs baseline: 1.8722x; 1.8722x over previous
#include <cuda_runtime.h>
#include <cuda_fp16.h>
#include <cstdint>
#include <math.h>

typedef unsigned int u32;

#define DM   1024
#define G4   4096
#define NB   128
#define NS   1024
#define NC   512
#define NCTA 128
#define PH_STEP 65536

// ---------------- device scratch (static, no allocation) ----------------
__device__ float g_G[NC * G4];              // 8 MB
__device__ u32   g_PH[NS * PH_STEP];        // 256 MB fp16 h history, fragment-packed
__device__ uint4 g_WpPack[8 * 64 * 4 * 32]; // 1 MB W_pred fp16 B-fragment order
__device__ int   g_bar[NS * 256];           // 8 spread counters/step (stride 32)

__device__ __forceinline__ u32 sm2u(const void* p) {
    u32 a;
    asm("{ .reg .u64 t; cvta.to.shared.u64 t, %1; cvt.u32.u64 %0, t; }" : "=r"(a) : "l"(p));
    return a;
}
#define CP_ASYNC16(dst, src) \
    asm volatile("cp.async.ca.shared.global [%0], [%1], 16;" :: "r"(dst), "l"(src))
#define CP_COMMIT() asm volatile("cp.async.commit_group;" ::: "memory")
#define CP_WAIT0()  asm volatile("cp.async.wait_group 0;" ::: "memory")

// ============ fp32 NT GEMM for G (known-good) ============
__global__ void gemm_nt_kernel(const float* __restrict__ A, const float* __restrict__ Bm,
                               const float* __restrict__ bias0, const float* __restrict__ bias1,
                               float* __restrict__ Cout, int M, int N, int K)
{
    __shared__ float As[16][64];
    __shared__ float Bs[16][64];
    const int tid = threadIdx.x;
    const int tx = tid & 15, ty = tid >> 4;
    const int mBase = blockIdx.x * 64, nBase = blockIdx.y * 64;
    const int la = tid >> 2, lk = (tid & 3) * 4;

    float acc[4][4];
#pragma unroll
    for (int i = 0; i < 4; i++)
#pragma unroll
        for (int j = 0; j < 4; j++) acc[i][j] = 0.f;

    for (int kc = 0; kc < K; kc += 16) {
        {
            float4 v = *reinterpret_cast<const float4*>(&A[(size_t)(mBase + la) * K + kc + lk]);
            As[lk + 0][la] = v.x; As[lk + 1][la] = v.y; As[lk + 2][la] = v.z; As[lk + 3][la] = v.w;
        }
        {
            float4 v = *reinterpret_cast<const float4*>(&Bm[(size_t)(nBase + la) * K + kc + lk]);
            Bs[lk + 0][la] = v.x; Bs[lk + 1][la] = v.y; Bs[lk + 2][la] = v.z; Bs[lk + 3][la] = v.w;
        }
        __syncthreads();
#pragma unroll
        for (int k = 0; k < 16; k++) {
            float4 a4 = *reinterpret_cast<const float4*>(&As[k][tx * 4]);
            float4 b4 = *reinterpret_cast<const float4*>(&Bs[k][ty * 4]);
            float a[4] = {a4.x, a4.y, a4.z, a4.w};
            float b[4] = {b4.x, b4.y, b4.z, b4.w};
#pragma unroll
            for (int i = 0; i < 4; i++)
#pragma unroll
                for (int j = 0; j < 4; j++)
                    acc[i][j] = fmaf(a[i], b[j], acc[i][j]);
        }
        __syncthreads();
    }
#pragma unroll
    for (int i = 0; i < 4; i++) {
        int row = mBase + tx * 4 + i;
#pragma unroll
        for (int j = 0; j < 4; j++) {
            int col = nBase + ty * 4 + j;
            Cout[(size_t)row * N + col] = acc[i][j] + bias0[col] + bias1[col];
        }
    }
}

// ---- fast, saturating-safe activations ----
__device__ __forceinline__ float fast_sigmoid(float x) { return 1.f / (1.f + __expf(-x)); }
__device__ __forceinline__ float fast_tanh(float x)    { return 1.f - 2.f / (1.f + __expf(2.f * x)); }

#define MMA16816(C, A0, A1, A2, A3, B0, B1)                                   \
    asm volatile(                                                             \
        "mma.sync.aligned.m16n8k16.row.col.f32.f16.f16.f32 "                  \
        "{%0,%1,%2,%3}, {%4,%5,%6,%7}, {%8,%9}, {%0,%1,%2,%3};"               \
        : "+f"(C[0]), "+f"(C[1]), "+f"(C[2]), "+f"(C[3])                      \
        : "r"(A0), "r"(A1), "r"(A2), "r"(A3), "r"(B0), "r"(B1))

// ============ pack W_pred -> fp16 B-fragment order (known-good) ============
__global__ void pack_wpred_kernel(const float* __restrict__ Wp)
{
    int idx = blockIdx.x * 256 + threadIdx.x;
    int lane = idx & 31, q = (idx >> 5) & 3, it = (idx >> 7) & 63, nb = idx >> 13;
    u32 v[4];
#pragma unroll
    for (int h = 0; h < 2; h++) {
        int t = 2 * q + h;
        int n = nb * 64 + t * 8 + (lane >> 2);
        const float* row = Wp + (size_t)n * DM;
        int j0 = it * 8 + (lane & 3), j1 = j0 + 4;
        __half2 p0 = __floats2half2_rn(row[2 * j0], row[2 * j0 + 1]);
        __half2 p1 = __floats2half2_rn(row[2 * j1], row[2 * j1 + 1]);
        v[2 * h + 0] = *reinterpret_cast<u32*>(&p0);
        v[2 * h + 1] = *reinterpret_cast<u32*>(&p1);
    }
    g_WpPack[idx] = make_uint4(v[0], v[1], v[2], v[3]);
}

// =========================================================================
// Persistent LSTM: exact R10 scheme; single change vs R10 = G rows staged
// into SMEM via cp.async at step top (overlaps mma loop; cell reads LDS).
// 128 CTAs x 256 threads. Warp w = (bh = w&1, q = w>>1): M=64, K=256, N=32.
// W_hh fragments in registers; split-K=4 via padded smem; R10 barrier.
// =========================================================================
#define RSTRIDE 36
#define GSTRIDE 36
#define RED_FLOATS (4 * 128 * RSTRIDE)   // 18432 floats
#define GS_FLOATS  (128 * GSTRIDE)       // 4608 floats
#define SMEM_BYTES ((RED_FLOATS + GS_FLOATS) * 4)   // 92160 B

__global__ void __launch_bounds__(256, 1)
lstm_mma_kernel(const int* __restrict__ x, const float* __restrict__ Whh)
{
    extern __shared__ float smem_f[];
    float* red = smem_f;
    float* Gs  = smem_f + RED_FLOATS;    // staged G rows [128 b][4 g][8 f] stride 36

    const int tid  = threadIdx.x;
    const int lane = tid & 31;
    const int w    = tid >> 5;           // 0..7
    const int bh   = w & 1;
    const int q    = w >> 1;
    const int d0   = blockIdx.x * 8;
    const int tig  = lane & 3;
    const int grp  = lane >> 2;

    // staging identity: thread -> (batch sb, half sh)
    const int sb = tid >> 1;
    const int sh = tid & 1;
    const u32 gsDst = sm2u(Gs) + (u32)(sb * (GSTRIDE * 4) + sh * 16);
    const float* gSrcBase = g_G + d0 + sh * 4;

    // ---- one-time: W_hh fragments -> registers (proven fragment math) ----
    u32 wreg[128];
    {
        const int kbase = q * 256 + 2 * tig;
#pragma unroll
        for (int it = 0; it < 16; it++) {
#pragma unroll
            for (int n = 0; n < 4; n++) {
                const float* Wr = Whh + (size_t)(n * DM + d0 + grp) * DM + kbase + it * 16;
                __half2 p0 = __floats2half2_rn(Wr[0], Wr[1]);
                __half2 p1 = __floats2half2_rn(Wr[8], Wr[9]);
                wreg[it * 8 + n * 2 + 0] = *reinterpret_cast<u32*>(&p0);
                wreg[it * 8 + n * 2 + 1] = *reinterpret_cast<u32*>(&p1);
            }
        }
    }

    // ---- cell-update ownership (proven R5 scheme) ----
    const int b_lo = w * 16 + grp;
    const int b_hi = b_lo + 8;
    const int k2   = (d0 >> 1) + tig;
    const int p8   = k2 & 7;
    const int slot = (p8 < 4) ? (2 * p8) : (2 * (p8 - 4) + 1);
    const int wIdx = (w * 8 + grp) * 1024 + ((k2 >> 3) * 8 + slot) * 2;

    int aBase[4];
#pragma unroll
    for (int t = 0; t < 4; t++)
        aBase[t] = ((4 * bh + t) * 8 + grp) * 1024 + 4 * tig + q * 256;

    float cr[4] = {0.f, 0.f, 0.f, 0.f};

    for (int s = 0; s < NS; s++) {
        // ---- stage G[x[s]] rows into SMEM via cp.async (overlaps the mma) ----
        {
            const int xv = __ldg(&x[s * NB + sb]);
            const float* src = gSrcBase + (size_t)xv * G4;
#pragma unroll
            for (int g = 0; g < 4; g++)
                CP_ASYNC16(gsDst + g * 32, src + g * DM);
            CP_COMMIT();
        }

        float acc[4][4][4];              // [mtile][ntile=gate][c]
#pragma unroll
        for (int t = 0; t < 4; t++)
#pragma unroll
            for (int n = 0; n < 4; n++)
#pragma unroll
                for (int jj = 0; jj < 4; jj++) acc[t][n][jj] = 0.f;

        if (s > 0) {
            const u32* ph = g_PH + (size_t)(s - 1) * PH_STEP;
#pragma unroll
            for (int it = 0; it < 16; it++) {
                uint4 a0 = *reinterpret_cast<const uint4*>(ph + aBase[0] + it * 16);
                uint4 a1 = *reinterpret_cast<const uint4*>(ph + aBase[1] + it * 16);
                uint4 a2 = *reinterpret_cast<const uint4*>(ph + aBase[2] + it * 16);
                uint4 a3 = *reinterpret_cast<const uint4*>(ph + aBase[3] + it * 16);
#pragma unroll
                for (int n = 0; n < 4; n++) {
                    u32 w0 = wreg[it * 8 + 2 * n], w1 = wreg[it * 8 + 2 * n + 1];
                    MMA16816(acc[0][n], a0.x, a0.y, a0.z, a0.w, w0, w1);
                    MMA16816(acc[1][n], a1.x, a1.y, a1.z, a1.w, w0, w1);
                    MMA16816(acc[2][n], a2.x, a2.y, a2.z, a2.w, w0, w1);
                    MMA16816(acc[3][n], a3.x, a3.y, a3.z, a3.w, w0, w1);
                }
            }
        }

        // ---- publish split-K partials ----
        {
            float* rq = red + q * (128 * RSTRIDE);
#pragma unroll
            for (int t = 0; t < 4; t++) {
                int r0 = 64 * bh + 16 * t + grp;
#pragma unroll
                for (int n = 0; n < 4; n++) {
                    int col = 8 * n + 2 * tig;
                    *reinterpret_cast<float2*>(rq + r0 * RSTRIDE + col) =
                        make_float2(acc[t][n][0], acc[t][n][1]);
                    *reinterpret_cast<float2*>(rq + (r0 + 8) * RSTRIDE + col) =
                        make_float2(acc[t][n][2], acc[t][n][3]);
                }
            }
        }
        CP_WAIT0();
        __syncthreads();

        // ---- reduce 4 quarters + thread-local LSTM cell update ----
        {
            float gl[4][2], gh[4][2];
#pragma unroll
            for (int g = 0; g < 4; g++) {
                float2 v = *reinterpret_cast<const float2*>(Gs + b_lo * GSTRIDE + g * 8 + 2 * tig);
                gl[g][0] = v.x; gl[g][1] = v.y;
                float2 u = *reinterpret_cast<const float2*>(Gs + b_hi * GSTRIDE + g * 8 + 2 * tig);
                gh[g][0] = u.x; gh[g][1] = u.y;
            }

            float sum[2][4][2];
#pragma unroll
            for (int g = 0; g < 4; g++) {
                float sLx = 0.f, sLy = 0.f, sHx = 0.f, sHy = 0.f;
#pragma unroll
                for (int qq = 0; qq < 4; qq++) {
                    const float* rq = red + qq * (128 * RSTRIDE);
                    float2 vL = *reinterpret_cast<const float2*>(rq + b_lo * RSTRIDE + 8 * g + 2 * tig);
                    float2 vH = *reinterpret_cast<const float2*>(rq + b_hi * RSTRIDE + 8 * g + 2 * tig);
                    sLx += vL.x; sLy += vL.y; sHx += vH.x; sHy += vH.y;
                }
                sum[0][g][0] = sLx; sum[0][g][1] = sLy;
                sum[1][g][0] = sHx; sum[1][g][1] = sHy;
            }

            u32 h2out[2];
#pragma unroll
            for (int p = 0; p < 2; p++) {
                float hv[2];
#pragma unroll
                for (int e = 0; e < 2; e++) {
                    float ai = sum[p][0][e] + (p ? gh[0][e] : gl[0][e]);
                    float af = sum[p][1][e] + (p ? gh[1][e] : gl[1][e]);
                    float ag = sum[p][2][e] + (p ? gh[2][e] : gl[2][e]);
                    float ao = sum[p][3][e] + (p ? gh[3][e] : gl[3][e]);

                    float iv = fast_sigmoid(ai);
                    float fv = fast_sigmoid(af);
                    float gv = fast_tanh(ag);
                    float ov = fast_sigmoid(ao);

                    float cnew = fmaf(fv, cr[p * 2 + e], iv * gv);
                    cr[p * 2 + e] = cnew;
                    hv[e] = ov * fast_tanh(cnew);
                }
                __half2 hh = __floats2half2_rn(hv[0], hv[1]);
                h2out[p] = *reinterpret_cast<u32*>(&hh);
            }
            *reinterpret_cast<uint2*>(g_PH + (size_t)s * PH_STEP + wIdx) =
                make_uint2(h2out[0], h2out[1]);
        }

        // ---- grid barrier: 8 spread counters, lane-parallel poll (proven R10) ----
        __syncthreads();
        __threadfence();
        if (w == 0) {
            if (lane == 0)
                atomicAdd(&g_bar[s * 256 + (blockIdx.x & 7) * 32], 1);
            int done;
            do {
                int v = (lane < 8)
                      ? *((volatile int*)&g_bar[s * 256 + lane * 32]) : 16;
                done = __all_sync(0xffffffffu, v >= 16);
            } while (!done);
        }
        __syncthreads();
        __threadfence();
    }
}

// Reset barrier counters for deterministic graph replay.
__global__ void reset_bar_kernel()
{
    g_bar[blockIdx.x * 256 + threadIdx.x] = 0;
}

// ============ logits: PH(fp16) @ W_pred^T + bias via warp mma (known-good) ============
__global__ void __launch_bounds__(256, 1)
logits_mma_kernel(const float* __restrict__ bias, float* __restrict__ out)
{
    extern __shared__ uint4 wb[];        // 8192 uint4 = 128 KB
    const int tid = threadIdx.x;
    const int lane = tid & 31, w = tid >> 5;
    const int nb = blockIdx.x, s = blockIdx.y;
    const int grp = lane >> 2, tig = lane & 3;

    for (int i = tid; i < 8192; i += 256) wb[i] = g_WpPack[nb * 8192 + i];
    __syncthreads();

    const u32* ph   = g_PH + (size_t)s * PH_STEP;
    const int aBase = (w * 8 + grp) * 1024 + 4 * tig;

    float acc[8][4];
#pragma unroll
    for (int t = 0; t < 8; t++)
#pragma unroll
        for (int j = 0; j < 4; j++) acc[t][j] = 0.f;

#pragma unroll 2
    for (int it = 0; it < 64; it++) {
        uint4 a = *reinterpret_cast<const uint4*>(ph + aBase + it * 16);
#pragma unroll
        for (int qq = 0; qq < 4; qq++) {
            uint4 wq = wb[it * 128 + qq * 32 + lane];
            MMA16816(acc[2 * qq],     a.x, a.y, a.z, a.w, wq.x, wq.y);
            MMA16816(acc[2 * qq + 1], a.x, a.y, a.z, a.w, wq.z, wq.w);
        }
    }

    const int bL = w * 16 + grp, bH = bL + 8;
#pragma unroll
    for (int t = 0; t < 8; t++) {
        int col = nb * 64 + t * 8 + 2 * tig;
        float2 bz = *reinterpret_cast<const float2*>(bias + col);
        *reinterpret_cast<float2*>(out + (size_t)bL * NS * NC + (size_t)s * NC + col) =
            make_float2(acc[t][0] + bz.x, acc[t][1] + bz.y);
        *reinterpret_cast<float2*>(out + (size_t)bH * NS * NC + (size_t)s * NC + col) =
            make_float2(acc[t][2] + bz.x, acc[t][3] + bz.y);
    }
}

// =========================================================================
extern "C" void kernel_launch(void* const* d_in, const int* in_sizes, int n_in,
                              void* d_out, int out_size)
{
    const int*   x      = (const int*)  d_in[0];
    const float* emb    = (const float*)d_in[1];
    const float* W_ih   = (const float*)d_in[2];
    const float* W_hh   = (const float*)d_in[3];
    const float* b_ih   = (const float*)d_in[4];
    const float* b_hh   = (const float*)d_in[5];
    const float* W_pred = (const float*)d_in[6];
    const float* b_pred = (const float*)d_in[7];
    float* out = (float*)d_out;

    float* Gp; cudaGetSymbolAddress((void**)&Gp, g_G);

    // 1) G = emb @ W_ih^T + b_ih + b_hh
    {
        dim3 grid(NC / 64, G4 / 64);
        gemm_nt_kernel<<<grid, 256>>>(emb, W_ih, b_ih, b_hh, Gp, NC, G4, DM);
    }
    // 2) pack W_pred
    pack_wpred_kernel<<<256, 256>>>(W_pred);
    // 3) persistent LSTM (R10 + cp.async G staging; R10 barrier)
    {
        cudaFuncSetAttribute(lstm_mma_kernel,
                             cudaFuncAttributeMaxDynamicSharedMemorySize, SMEM_BYTES);
        lstm_mma_kernel<<<NCTA, 256, SMEM_BYTES>>>(x, W_hh);
    }
    // 4) reset barrier counters
    reset_bar_kernel<<<NS, 256>>>();
    // 5) logits
    {
        const int smem_bytes = 8192 * (int)sizeof(uint4);
        cudaFuncSetAttribute(logits_mma_kernel,
                             cudaFuncAttributeMaxDynamicSharedMemorySize, smem_bytes);
        dim3 grid(8, NS);
        logits_mma_kernel<<<grid, 256, smem_bytes>>>(b_pred, out);
    }
}